// round 6
// baseline (speedup 1.0000x reference)
#include <cuda_runtime.h>

#define GN    128
#define GN2   (GN * GN)
#define GN3   (GN * GN * GN)
#define NROWS (GN * GN)        /* 16384 k-rows, one 32-bit mask word each */
#define BIGV  1.0e5f
#define NITER 128

// Allocation-free scratch: ping-pong u buffers, change masks, barrier state.
__device__ float        g_bufA[GN3];
__device__ float        g_bufB[GN3];
__device__ unsigned int g_mask[2][NROWS];      // bit c = float4-group c changed
__device__ unsigned int          g_bar_count = 0;
__device__ volatile unsigned int g_bar_sense = 0;

__global__ void __launch_bounds__(256, 6) eik_persist(
    const float* __restrict__ u0,
    const float* __restrict__ f,
    float* __restrict__ out,
    int nblocks)
{
    const int lane   = threadIdx.x;                 // 0..31: k in float4s
    const int gwarp  = blockIdx.x * 8 + threadIdx.y;
    const int nwarps = nblocks * 8;
    const unsigned FULL = 0xffffffffu;

    unsigned int local_sense = 0;
    const float* src = u0;

    for (int it = 0; it < NITER; ++it) {
        float* dst = (it == NITER - 1) ? out : ((it & 1) ? g_bufB : g_bufA);
        const unsigned int* mprev = g_mask[(it + 1) & 1];
        unsigned int*       mcur  = g_mask[it & 1];
        const bool use_skip   = (it >= 2);     // both buffers + masks primed
        const bool write_mask = (it < NITER - 1);
        const bool last       = (it == NITER - 1);

        for (int r = gwarp; r < NROWS; r += nwarps) {
            const int i   = r >> 7;
            const int j   = r & 127;
            const int idx = r * GN + lane * 4;

            // ---- change-mask skip test (warp-uniform result) ----
            // Skip group c iff no dependency group changed at it-1:
            //   bits c-1,c,c+1 of own row (z-neighbors + own cells' intra-row
            //   neighbors) and bit c of rows i±1, j±1. Own-bit inclusion also
            //   guarantees dst (holding u(it-1)) already equals u(it)=u(it+1).
            unsigned int W = FULL;
            if (use_skip) {
                unsigned int m = 0;
                if (lane == 0)                 m = mprev[r];
                else if (lane == 1 && i > 0)   m = mprev[r - GN];
                else if (lane == 2 && i < 127) m = mprev[r + GN];
                else if (lane == 3 && j > 0)   m = mprev[r - 1];
                else if (lane == 4 && j < 127) m = mprev[r + 1];
                const unsigned int cm = __shfl_sync(FULL, m, 0);
                const unsigned int nb = __shfl_sync(FULL, m, 1) |
                                        __shfl_sync(FULL, m, 2) |
                                        __shfl_sync(FULL, m, 3) |
                                        __shfl_sync(FULL, m, 4);
                W = nb | cm | (cm << 1) | (cm >> 1);
            }

            if (W == 0) {                       // whole row quiet
                if (last) {                     // d_out is poisoned: copy through
                    *(float4*)(dst + idx) = *(const float4*)(src + idx);
                }
                if (write_mask && lane == 0) mcur[r] = 0;
                continue;
            }

            // ---- full row compute (wavefront shell) ----
            const float4 big4 = make_float4(BIGV, BIGV, BIGV, BIGV);
            const float4 uc  = *(const float4*)(src + idx);
            const float4 xm4 = (i > 0)   ? *(const float4*)(src + idx - GN2) : big4;
            const float4 xp4 = (i < 127) ? *(const float4*)(src + idx + GN2) : big4;
            const float4 ym4 = (j > 0)   ? *(const float4*)(src + idx - GN)  : big4;
            const float4 yp4 = (j < 127) ? *(const float4*)(src + idx + GN)  : big4;

            float left  = __shfl_up_sync(FULL, uc.w, 1);
            float right = __shfl_down_sync(FULL, uc.x, 1);
            if (lane == 0)  left  = BIGV;
            if (lane == 31) right = BIGV;

            const float* ucp = (const float*)&uc;
            const float* xmp = (const float*)&xm4;
            const float* xpp = (const float*)&xp4;
            const float* ymp = (const float*)&ym4;
            const float* ypp = (const float*)&yp4;

            bool act[4];
            bool anyact = false;
            #pragma unroll
            for (int c = 0; c < 4; ++c) {
                const float zm = (c == 0) ? left  : ucp[c - 1];
                const float zp = (c == 3) ? right : ucp[c + 1];
                const float a1 = fminf(fminf(fminf(xmp[c], xpp[c]),
                                             fminf(ymp[c], ypp[c])),
                                       fminf(zm, zp));
                act[c] = (a1 < ucp[c]);     // monotone: else min(u,x)==u
                anyact |= act[c];
            }

            float4 res = uc;
            float* rp = (float*)&res;
            if (anyact) {
                const float4 f4 = *(const float4*)(f + idx);
                const float* fp = (const float*)&f4;
                #pragma unroll
                for (int c = 0; c < 4; ++c) {
                    if (!act[c]) continue;
                    const float zm = (c == 0) ? left  : ucp[c - 1];
                    const float zp = (c == 3) ? right : ucp[c + 1];
                    const float ax = fminf(xmp[c], xpp[c]);
                    const float ay = fminf(ymp[c], ypp[c]);
                    const float az = fminf(zm, zp);
                    // exact 3-sort via min/max network (matches jnp.sort)
                    const float a1 = fminf(ax, fminf(ay, az));
                    const float a3 = fmaxf(ax, fmaxf(ay, az));
                    const float a2 = fmaxf(fminf(ax, ay),
                                           fminf(fmaxf(ax, ay), az));
                    const float fh = fp[c];                 // h == 1.0
                    const float x1 = a1 + fh;
                    float x;
                    if (x1 <= a2) {
                        x = x1;
                    } else {
                        const float d  = a1 - a2;
                        const float d2 = 2.0f * fh * fh - d * d;
                        const float x2 = 0.5f * (a1 + a2 + sqrtf(fmaxf(d2, 0.0f)));
                        if (x2 <= a3) {
                            x = x2;
                        } else {
                            const float s  = a1 + a2 + a3;
                            const float q  = a1 * a1 + a2 * a2 + a3 * a3;
                            const float d3 = s * s - 3.0f * (q - fh * fh);
                            x = (s + sqrtf(fmaxf(d3, 0.0f))) / 3.0f;
                        }
                    }
                    rp[c] = fminf(ucp[c], x);
                }
            }

            *(float4*)(dst + idx) = res;

            if (write_mask) {
                const ulonglong2 a = *(const ulonglong2*)&res;
                const ulonglong2 b = *(const ulonglong2*)&uc;
                const bool changed = (a.x != b.x) || (a.y != b.y);
                const unsigned int bal = __ballot_sync(FULL, changed);
                if (lane == 0) mcur[r] = bal;
            }
        }

        // ---- software grid barrier (sense reversal; state self-restores) ----
        local_sense ^= 1u;
        __syncthreads();
        if (threadIdx.x == 0 && threadIdx.y == 0) {
            __threadfence();
            unsigned int old = atomicInc(&g_bar_count, (unsigned)nblocks - 1u);
            if (old == (unsigned)nblocks - 1u) {
                g_bar_sense = local_sense;
            } else {
                while (g_bar_sense != local_sense) __nanosleep(32);
            }
            __threadfence();
        }
        __syncthreads();

        src = dst;
    }
}

extern "C" void kernel_launch(void* const* d_in, const int* in_sizes, int n_in,
                              void* d_out, int out_size)
{
    const float* u0 = (const float*)d_in[0];
    const float* f  = (const float*)d_in[1];
    float* out      = (float*)d_out;

    int dev = 0;
    cudaGetDevice(&dev);
    int sms = 0;
    cudaDeviceGetAttribute(&sms, cudaDevAttrMultiProcessorCount, dev);
    int bpsm = 0;
    cudaOccupancyMaxActiveBlocksPerMultiprocessor(&bpsm, eik_persist, 256, 0);
    if (bpsm < 1) bpsm = 1;
    int nblocks = sms * bpsm;
    if (nblocks > NROWS / 8) nblocks = NROWS / 8;

    const dim3 blk(32, 8, 1);
    eik_persist<<<nblocks, blk>>>(u0, f, out, nblocks);
}

// round 7
// speedup vs baseline: 1.1140x; 1.1140x over previous
#include <cuda_runtime.h>

#define GN    128
#define GN2   (GN * GN)
#define GN3   (GN * GN * GN)
#define NROWS (GN * GN)
#define BIGV  1.0e5f
#define NITER 128

// Allocation-free scratch: ping-pong u buffers + ping-pong change masks.
__device__ float        g_bufA[GN3];
__device__ float        g_bufB[GN3];
__device__ unsigned int g_maskA[NROWS];   // bit c = float4-group c changed
__device__ unsigned int g_maskB[NROWS];

__global__ void __launch_bounds__(256) eik_step(
    const float* __restrict__ src,
    const float* __restrict__ f,
    float* __restrict__ dst,
    const unsigned int* __restrict__ mprev,
    unsigned int* __restrict__ mcur,
    const int mode)   // bit0: use_skip, bit1: write_mask, bit2: last (force store)
{
    const unsigned FULL = 0xffffffffu;
    const int lane = threadIdx.x;                    // 0..31: k in float4s
    const int j = blockIdx.y * 8 + threadIdx.y;
    const int i = blockIdx.z;
    const int r = i * GN + j;
    const int idx = r * GN + lane * 4;

    const bool use_skip   = mode & 1;
    const bool write_mask = mode & 2;
    const bool last       = mode & 4;

    // ---- change-mask gather: dependency word W (warp-uniform) ----
    // Lane c may change at t only if a dependency group changed at t-1:
    // bits c-1,c,c+1 of own row (z/own) and bit c of rows i±1, j±1.
    unsigned int W = FULL;
    if (use_skip) {
        unsigned int m = 0;
        if (lane == 0)                 m = mprev[r];
        else if (lane == 1 && i > 0)   m = mprev[r - GN];
        else if (lane == 2 && i < 127) m = mprev[r + GN];
        else if (lane == 3 && j > 0)   m = mprev[r - 1];
        else if (lane == 4 && j < 127) m = mprev[r + 1];
        const unsigned int cm = __shfl_sync(FULL, m, 0);
        const unsigned int nb = __shfl_sync(FULL, m, 1) | __shfl_sync(FULL, m, 2) |
                                __shfl_sync(FULL, m, 3) | __shfl_sync(FULL, m, 4);
        W = nb | cm | (cm << 1) | (cm >> 1);
    }

    if (W == 0) {                                    // whole row quiet
        if (last) {                                  // d_out poisoned: copy through
            *(float4*)(dst + idx) = *(const float4*)(src + idx);
        } else if (write_mask && lane == 0) {
            mcur[r] = 0;
        }
        return;
    }

    // uc is always loaded (active neighbors need it via shfl)
    const float4 uc = *(const float4*)(src + idx);
    float left  = __shfl_up_sync(FULL, uc.w, 1);
    float right = __shfl_down_sync(FULL, uc.x, 1);
    if (lane == 0)  left  = BIGV;
    if (lane == 31) right = BIGV;

    const bool active = ((W >> lane) & 1u) != 0u;

    float4 res = uc;
    bool changed = false;

    if (active) {
        const float4 big4 = make_float4(BIGV, BIGV, BIGV, BIGV);
        const float4 xm4 = (i > 0)   ? *(const float4*)(src + idx - GN2) : big4;
        const float4 xp4 = (i < 127) ? *(const float4*)(src + idx + GN2) : big4;
        const float4 ym4 = (j > 0)   ? *(const float4*)(src + idx - GN)  : big4;
        const float4 yp4 = (j < 127) ? *(const float4*)(src + idx + GN)  : big4;

        const float* ucp = (const float*)&uc;
        const float* xmp = (const float*)&xm4;
        const float* xpp = (const float*)&xp4;
        const float* ymp = (const float*)&ym4;
        const float* ypp = (const float*)&yp4;

        bool act[4];
        bool anyact = false;
        #pragma unroll
        for (int c = 0; c < 4; ++c) {
            const float zm = (c == 0) ? left  : ucp[c - 1];
            const float zp = (c == 3) ? right : ucp[c + 1];
            const float a1 = fminf(fminf(fminf(xmp[c], xpp[c]),
                                         fminf(ymp[c], ypp[c])),
                                   fminf(zm, zp));
            act[c] = (a1 < ucp[c]);      // monotone: else min(u,x)==u
            anyact |= act[c];
        }

        float* rp = (float*)&res;
        if (anyact) {
            const float4 f4 = *(const float4*)(f + idx);
            const float* fp = (const float*)&f4;
            #pragma unroll
            for (int c = 0; c < 4; ++c) {
                if (!act[c]) continue;
                const float zm = (c == 0) ? left  : ucp[c - 1];
                const float zp = (c == 3) ? right : ucp[c + 1];
                const float ax = fminf(xmp[c], xpp[c]);
                const float ay = fminf(ymp[c], ypp[c]);
                const float az = fminf(zm, zp);
                // exact 3-sort via min/max network (matches jnp.sort)
                const float a1 = fminf(ax, fminf(ay, az));
                const float a3 = fmaxf(ax, fmaxf(ay, az));
                const float a2 = fmaxf(fminf(ax, ay), fminf(fmaxf(ax, ay), az));
                const float fh = fp[c];                 // h == 1.0
                const float x1 = a1 + fh;
                float x;
                if (x1 <= a2) {
                    x = x1;
                } else {
                    const float d  = a1 - a2;
                    const float d2 = 2.0f * fh * fh - d * d;
                    const float x2 = 0.5f * (a1 + a2 + sqrtf(fmaxf(d2, 0.0f)));
                    if (x2 <= a3) {
                        x = x2;
                    } else {
                        const float s  = a1 + a2 + a3;
                        const float q  = a1 * a1 + a2 * a2 + a3 * a3;
                        const float d3 = s * s - 3.0f * (q - fh * fh);
                        x = (s + sqrtf(fmaxf(d3, 0.0f))) / 3.0f;
                    }
                }
                rp[c] = fminf(ucp[c], x);
            }
        }
        const ulonglong2 a = *(const ulonglong2*)&res;
        const ulonglong2 b = *(const ulonglong2*)&uc;
        changed = (a.x != b.x) || (a.y != b.y);
    }

    // Store: active lanes (value may differ; dst holds stale u(t-2)),
    // plus everyone on the last iteration (d_out poisoned).
    if (active || last) {
        *(float4*)(dst + idx) = res;
    }

    if (write_mask) {
        const unsigned int bal = __ballot_sync(FULL, changed);
        if (lane == 0) mcur[r] = bal;
    }
}

extern "C" void kernel_launch(void* const* d_in, const int* in_sizes, int n_in,
                              void* d_out, int out_size)
{
    const float* u0 = (const float*)d_in[0];
    const float* f  = (const float*)d_in[1];
    float* out      = (float*)d_out;

    float *bufA = nullptr, *bufB = nullptr;
    unsigned int *maskA = nullptr, *maskB = nullptr;
    cudaGetSymbolAddress((void**)&bufA, g_bufA);
    cudaGetSymbolAddress((void**)&bufB, g_bufB);
    cudaGetSymbolAddress((void**)&maskA, g_maskA);
    cudaGetSymbolAddress((void**)&maskB, g_maskB);

    const dim3 blk(32, 8, 1);
    const dim3 grd(1, GN / 8, GN);

    const float* src = u0;
    for (int it = 0; it < NITER; ++it) {
        float* dst = (it == NITER - 1) ? out : ((it & 1) ? bufB : bufA);
        unsigned int* mcur        = (it & 1) ? maskB : maskA;
        const unsigned int* mprev = (it & 1) ? maskA : maskB;
        int mode = 0;
        if (it >= 2)         mode |= 1;   // use_skip (masks+buffers primed)
        if (it < NITER - 1)  mode |= 2;   // write_mask
        if (it == NITER - 1) mode |= 4;   // last: force store into d_out
        eik_step<<<grd, blk>>>(src, f, dst, mprev, mcur, mode);
        src = dst;
    }
}